// round 1
// baseline (speedup 1.0000x reference)
#include <cuda_runtime.h>
#include <cstdint>

#define CC 32
#define TT 2048
#define EMB 1024
#define NH 16
#define DH 64
#define MAPD 4096
#define NROWS (CC*TT)          // 65536
#define NVEC (NROWS*NH)        // 1048576
#define EPS_LN 1e-5f

// ---------------- scratch (static device globals; no allocation) ----------------
__device__ float g_M[DH*DH];                    // Wq^T Wk
__device__ float g_xsum[CC*EMB];                // sum over t of inp
__device__ float g_vsum[CC*EMB];                // Wv @ xsum per head
__device__ float g_w[NROWS*NH];                 // diag scores -> softmax weights
__device__ float g_y[(size_t)NROWS*EMB];        // LN1 output (268 MB)
__device__ float g_h[(size_t)NROWS*MAPD];       // fc1 output (1.07 GB)

// ---------------- packed f32x2 helpers (sm_103a) ----------------
__device__ __forceinline__ unsigned long long pk2(float lo, float hi){
    unsigned long long r;
    asm("mov.b64 %0, {%1, %2};" : "=l"(r) : "f"(lo), "f"(hi));
    return r;
}
__device__ __forceinline__ void upk2(unsigned long long v, float& lo, float& hi){
    asm("mov.b64 {%0, %1}, %2;" : "=f"(lo), "=f"(hi) : "l"(v));
}
__device__ __forceinline__ void fma2(unsigned long long& d, unsigned long long a, unsigned long long b){
    asm("fma.rn.f32x2 %0, %1, %2, %0;" : "+l"(d) : "l"(a), "l"(b));
}

// ---------------- small prep kernels ----------------
__global__ void k_zero_xsum(){
    int i = blockIdx.x*256 + threadIdx.x;
    if(i < CC*EMB) g_xsum[i] = 0.f;
}

__global__ void k_prep_M(const float* __restrict__ wq, const float* __restrict__ wk){
    __shared__ float sq[DH*DH], sk[DH*DH];
    for(int i=threadIdx.x;i<DH*DH;i+=256){ sq[i]=wq[i]; sk[i]=wk[i]; }
    __syncthreads();
    for(int idx=threadIdx.x; idx<DH*DH; idx+=256){
        int d = idx/DH, e = idx%DH;
        float s = 0.f;
        #pragma unroll
        for(int o=0;o<DH;o++) s += sq[o*DH+d]*sk[o*DH+e];
        g_M[idx] = s;
    }
}

// sum over T of inp -> g_xsum[c][e]; grid (32, 16), 256 threads
__global__ void k_xsum(const float* __restrict__ inp){
    int c = blockIdx.x, ch = blockIdx.y;
    const float* base = inp + ((size_t)c*TT + (size_t)ch*(TT/16))*EMB + threadIdx.x;
    float a0=0.f,a1=0.f,a2=0.f,a3=0.f;
    for(int t=0;t<TT/16;t++){
        const float* r = base + (size_t)t*EMB;
        a0 += r[0]; a1 += r[256]; a2 += r[512]; a3 += r[768];
    }
    atomicAdd(&g_xsum[c*EMB + threadIdx.x      ], a0);
    atomicAdd(&g_xsum[c*EMB + threadIdx.x + 256], a1);
    atomicAdd(&g_xsum[c*EMB + threadIdx.x + 512], a2);
    atomicAdd(&g_xsum[c*EMB + threadIdx.x + 768], a3);
}

// vsum[c,h,o] = sum_d xsum[c,h,d]*wv[o,d]; grid 512 blocks of 64
__global__ void k_vsum(const float* __restrict__ wv){
    int c = blockIdx.x>>4, h = blockIdx.x&15;
    __shared__ float xs[DH];
    int o = threadIdx.x;
    xs[o] = g_xsum[c*EMB + h*DH + o];
    __syncthreads();
    float s = 0.f;
    #pragma unroll
    for(int d=0;d<DH;d++) s += xs[d]*wv[o*DH+d];
    g_vsum[c*EMB + h*DH + o] = s;
}

// diag[g] = x_g^T M x_g / 32 for g in [0, NVEC); register-blocked batched matvec.
// grid = NVEC/64 blocks, 256 threads (16x16), each thread 4 rows x 4 cols.
__global__ __launch_bounds__(256) void k_diag(const float* __restrict__ inp){
    __shared__ float Ms[DH][DH];     // [d][e]
    __shared__ float Xs[64][DH+1];
    __shared__ float ds[64];
    int g0 = blockIdx.x*64;
    int tid = threadIdx.x, tx = tid&15, ty = tid>>4;
    for(int i=tid;i<DH*DH;i+=256) (&Ms[0][0])[i] = g_M[i];
    {
        const float* src = inp + (size_t)g0*DH;
        for(int i=tid;i<64*(DH/4);i+=256){
            int r = i/(DH/4), q = i%(DH/4);
            float4 v = *(const float4*)(src + (size_t)r*DH + q*4);
            Xs[r][q*4+0]=v.x; Xs[r][q*4+1]=v.y; Xs[r][q*4+2]=v.z; Xs[r][q*4+3]=v.w;
        }
    }
    __syncthreads();
    float acc[4][4] = {};
    #pragma unroll 8
    for(int k=0;k<DH;k++){
        float a[4], b[4];
        #pragma unroll
        for(int i=0;i<4;i++) a[i] = Xs[ty*4+i][k];
        #pragma unroll
        for(int j=0;j<4;j++) b[j] = Ms[k][tx*4+j];
        #pragma unroll
        for(int i=0;i<4;i++)
            #pragma unroll
            for(int j=0;j<4;j++) acc[i][j] += a[i]*b[j];
    }
    #pragma unroll
    for(int i=0;i<4;i++){
        float p = 0.f;
        #pragma unroll
        for(int j=0;j<4;j++) p += acc[i][j]*Xs[ty*4+i][tx*4+j];
        #pragma unroll
        for(int off=8;off;off>>=1) p += __shfl_down_sync(0xffffffffu, p, off, 16);
        if(tx==0) ds[ty*4+i] = p;
    }
    __syncthreads();
    if(tid < 64) g_w[g0+tid] = ds[tid]*(1.0f/32.0f);
}

// softmax over C (stride TT*NH) in place on g_w; one thread per (t,h)
__global__ void k_softmax(){
    int i = blockIdx.x*256 + threadIdx.x;
    if(i >= TT*NH) return;
    float v[CC];
    float m = -1e30f;
    #pragma unroll
    for(int c=0;c<CC;c++){ v[c] = g_w[(size_t)c*(TT*NH) + i]; m = fmaxf(m, v[c]); }
    float s = 0.f;
    #pragma unroll
    for(int c=0;c<CC;c++){ v[c] = __expf(v[c]-m); s += v[c]; }
    float inv = 1.f/s;
    #pragma unroll
    for(int c=0;c<CC;c++) g_w[(size_t)c*(TT*NH) + i] = v[c]*inv;
}

// ---------------- block reduction ----------------
__device__ __forceinline__ float blk_reduce(float v, float* red){
    int lane = threadIdx.x&31, w = threadIdx.x>>5;
    #pragma unroll
    for(int off=16;off;off>>=1) v += __shfl_down_sync(0xffffffffu, v, off);
    if(lane==0) red[w] = v;
    __syncthreads();
    if(w==0){
        float x = (lane<8)? red[lane] : 0.f;
        #pragma unroll
        for(int off=4;off;off>>=1) x += __shfl_down_sync(0xffffffffu, x, off);
        if(lane==0) red[0] = x;
    }
    __syncthreads();
    float r = red[0];
    __syncthreads();
    return r;
}

// x2 = inp + attn; y = x2 + LN1(x2); one block per row
__global__ __launch_bounds__(256) void k_ln1(const float* __restrict__ inp,
                                             const float* __restrict__ g1,
                                             const float* __restrict__ b1){
    __shared__ float red[8];
    __shared__ float ws[NH];
    int row = blockIdx.x, c = row>>11;
    int tid = threadIdx.x;
    if(tid < NH) ws[tid] = g_w[(size_t)row*NH + tid];
    __syncthreads();
    float x[4]; float s = 0.f;
    #pragma unroll
    for(int j=0;j<4;j++){
        int e = tid + j*256;
        float v = inp[(size_t)row*EMB + e] + ws[e>>6]*g_vsum[c*EMB + e];
        x[j] = v; s += v;
    }
    float mu = blk_reduce(s, red)*(1.f/EMB);
    float q = 0.f;
    #pragma unroll
    for(int j=0;j<4;j++){ float d = x[j]-mu; q += d*d; }
    float rstd = rsqrtf(blk_reduce(q, red)*(1.f/EMB) + EPS_LN);
    #pragma unroll
    for(int j=0;j<4;j++){
        int e = tid + j*256;
        g_y[(size_t)row*EMB + e] = x[j] + (x[j]-mu)*rstd*g1[e] + b1[e];
    }
}

// final LN2 in place on out
__global__ __launch_bounds__(256) void k_ln2(float* __restrict__ out,
                                             const float* __restrict__ g2,
                                             const float* __restrict__ b2){
    __shared__ float red[8];
    int row = blockIdx.x;
    int tid = threadIdx.x;
    float x[4]; float s = 0.f;
    #pragma unroll
    for(int j=0;j<4;j++){
        int e = tid + j*256;
        x[j] = out[(size_t)row*EMB + e]; s += x[j];
    }
    float mu = blk_reduce(s, red)*(1.f/EMB);
    float q = 0.f;
    #pragma unroll
    for(int j=0;j<4;j++){ float d = x[j]-mu; q += d*d; }
    float rstd = rsqrtf(blk_reduce(q, red)*(1.f/EMB) + EPS_LN);
    #pragma unroll
    for(int j=0;j<4;j++){
        int e = tid + j*256;
        out[(size_t)row*EMB + e] = (x[j]-mu)*rstd*g2[e] + b2[e];
    }
}

// ---------------- GEMM: C[M,N] = A[M,K] @ B[N,K]^T + bias ----------------
// 128x128 tile, BK=16, 256 threads, 8x8 per thread, packed f32x2 FMA.
__global__ __launch_bounds__(256) void k_gemm(
    const float* __restrict__ A, const float* __restrict__ B,
    const float* __restrict__ bias, float* __restrict__ Cm,
    int M, int N, int K){
    const int BM=128, BN=128, BK=16;
    __shared__ float As[BK][BM+4];
    __shared__ float Bs[BK][BN+4];
    int tid = threadIdx.x;
    size_t bm = (size_t)blockIdx.y*BM, bn = (size_t)blockIdx.x*BN;
    int tx = tid&15, ty = tid>>4;

    unsigned long long acc[8][4];
    #pragma unroll
    for(int i=0;i<8;i++)
        #pragma unroll
        for(int jp=0;jp<4;jp++) acc[i][jp] = 0ull;

    const float* Ab = A + bm*(size_t)K;
    const float* Bb = B + bn*(size_t)K;
    int r0 = tid>>2;            // 0..63
    int kv = (tid&3)<<2;        // 0,4,8,12

    for(int k0=0;k0<K;k0+=BK){
        #pragma unroll
        for(int i=0;i<2;i++){
            int r = r0 + i*64;
            float4 va = *(const float4*)(Ab + (size_t)r*K + k0 + kv);
            As[kv+0][r]=va.x; As[kv+1][r]=va.y; As[kv+2][r]=va.z; As[kv+3][r]=va.w;
            float4 vb = *(const float4*)(Bb + (size_t)r*K + k0 + kv);
            Bs[kv+0][r]=vb.x; Bs[kv+1][r]=vb.y; Bs[kv+2][r]=vb.z; Bs[kv+3][r]=vb.w;
        }
        __syncthreads();
        #pragma unroll
        for(int k=0;k<BK;k++){
            float a[8];
            *(float4*)(a)   = *(const float4*)&As[k][ty*8];
            *(float4*)(a+4) = *(const float4*)&As[k][ty*8+4];
            float4 b0 = *(const float4*)&Bs[k][tx*8];
            float4 b1 = *(const float4*)&Bs[k][tx*8+4];
            unsigned long long bp0 = pk2(b0.x,b0.y);
            unsigned long long bp1 = pk2(b0.z,b0.w);
            unsigned long long bp2 = pk2(b1.x,b1.y);
            unsigned long long bp3 = pk2(b1.z,b1.w);
            #pragma unroll
            for(int i=0;i<8;i++){
                unsigned long long ap = pk2(a[i], a[i]);
                fma2(acc[i][0], ap, bp0);
                fma2(acc[i][1], ap, bp1);
                fma2(acc[i][2], ap, bp2);
                fma2(acc[i][3], ap, bp3);
            }
        }
        __syncthreads();
    }

    const float* bb = bias + bn + tx*8;
    float4 bi0 = *(const float4*)(bb);
    float4 bi1 = *(const float4*)(bb+4);
    #pragma unroll
    for(int i=0;i<8;i++){
        float v[8];
        upk2(acc[i][0], v[0], v[1]);
        upk2(acc[i][1], v[2], v[3]);
        upk2(acc[i][2], v[4], v[5]);
        upk2(acc[i][3], v[6], v[7]);
        float4 o0, o1;
        o0.x = v[0]+bi0.x; o0.y = v[1]+bi0.y; o0.z = v[2]+bi0.z; o0.w = v[3]+bi0.w;
        o1.x = v[4]+bi1.x; o1.y = v[5]+bi1.y; o1.z = v[6]+bi1.z; o1.w = v[7]+bi1.w;
        float* crow = Cm + (bm + ty*8 + i)*(size_t)N + bn + tx*8;
        *(float4*)(crow)   = o0;
        *(float4*)(crow+4) = o1;
    }
}

// ---------------- launch ----------------
extern "C" void kernel_launch(void* const* d_in, const int* in_sizes, int n_in,
                              void* d_out, int out_size){
    const float* inp   = (const float*)d_in[0];
    const float* wq    = (const float*)d_in[1];
    const float* wk    = (const float*)d_in[2];
    const float* wv    = (const float*)d_in[3];
    const float* ln1_g = (const float*)d_in[4];
    const float* ln1_b = (const float*)d_in[5];
    const float* fc1_w = (const float*)d_in[6];
    const float* fc1_b = (const float*)d_in[7];
    const float* fc2_w = (const float*)d_in[8];
    const float* fc2_b = (const float*)d_in[9];
    const float* ln2_g = (const float*)d_in[10];
    const float* ln2_b = (const float*)d_in[11];
    float* out = (float*)d_out;

    float *yp = nullptr, *hp = nullptr;
    cudaGetSymbolAddress((void**)&yp, g_y);
    cudaGetSymbolAddress((void**)&hp, g_h);

    k_zero_xsum<<<(CC*EMB+255)/256, 256>>>();
    k_prep_M<<<1, 256>>>(wq, wk);
    k_xsum<<<dim3(CC,16), 256>>>(inp);
    k_vsum<<<CC*NH, 64>>>(wv);
    k_diag<<<NVEC/64, 256>>>(inp);
    k_softmax<<<(TT*NH+255)/256, 256>>>();
    k_ln1<<<NROWS, 256>>>(inp, ln1_g, ln1_b);
    // h = y @ fc1_w^T + fc1_b
    k_gemm<<<dim3(MAPD/128, NROWS/128), 256>>>(yp, fc1_w, fc1_b, hp, NROWS, MAPD, EMB);
    // out = h @ fc2_w^T + fc2_b
    k_gemm<<<dim3(EMB/128, NROWS/128), 256>>>(hp, fc2_w, fc2_b, out, NROWS, EMB, MAPD);
    k_ln2<<<NROWS, 256>>>(out, ln2_g, ln2_b);
}

// round 3
// speedup vs baseline: 2.2113x; 2.2113x over previous
#include <cuda_runtime.h>
#include <cuda_bf16.h>
#include <cstdint>

#define CC 32
#define TT 2048
#define EMB 1024
#define NH 16
#define DH 64
#define MAPD 4096
#define NROWS (CC*TT)          // 65536
#define NVEC (NROWS*NH)
#define EPS_LN 1e-5f

// ---------------- scratch (static device globals) ----------------
__device__ float g_M[DH*DH];
__device__ float g_xsum[CC*EMB];
__device__ float g_vsum[CC*EMB];
__device__ float g_w[NROWS*NH];
// split-bf16 interleaved: row-major [rows][2*K], each 32-k block stored [hi(32)|lo(32)]
__device__ __align__(128) __nv_bfloat16 g_y2[(size_t)NROWS*(2*EMB)];    // 268 MB
__device__ __align__(128) __nv_bfloat16 g_h2[(size_t)NROWS*(2*MAPD)];   // 1.07 GB
__device__ __align__(128) __nv_bfloat16 g_w1[(size_t)MAPD*(2*EMB)];     // 16 MB
__device__ __align__(128) __nv_bfloat16 g_w2[(size_t)EMB*(2*MAPD)];     // 16 MB

// ---------------- helpers ----------------
__device__ __forceinline__ uint32_t smem_u32(const void* p){
    uint32_t a;
    asm("{ .reg .u64 t; cvta.to.shared.u64 t, %1; cvt.u32.u64 %0, t; }" : "=r"(a) : "l"(p));
    return a;
}
__device__ __forceinline__ void cp16(uint32_t dst, const void* src){
    asm volatile("cp.async.cg.shared.global [%0], [%1], 16;" :: "r"(dst), "l"(src) : "memory");
}
__device__ __forceinline__ void cp_commit(){ asm volatile("cp.async.commit_group;" ::: "memory"); }
__device__ __forceinline__ void cp_wait2(){ asm volatile("cp.async.wait_group 2;" ::: "memory"); }
__device__ __forceinline__ void cp_wait0(){ asm volatile("cp.async.wait_group 0;" ::: "memory"); }

__device__ __forceinline__ void ldm4(uint32_t a, uint32_t& r0, uint32_t& r1, uint32_t& r2, uint32_t& r3){
    asm volatile("ldmatrix.sync.aligned.m8n8.x4.shared.b16 {%0,%1,%2,%3}, [%4];"
        : "=r"(r0), "=r"(r1), "=r"(r2), "=r"(r3) : "r"(a));
}
__device__ __forceinline__ void mma16816(float* d, uint32_t a0, uint32_t a1, uint32_t a2, uint32_t a3,
                                         uint32_t b0, uint32_t b1){
    asm volatile("mma.sync.aligned.m16n8k16.row.col.f32.bf16.bf16.f32 "
        "{%0,%1,%2,%3}, {%4,%5,%6,%7}, {%8,%9}, {%0,%1,%2,%3};"
        : "+f"(d[0]), "+f"(d[1]), "+f"(d[2]), "+f"(d[3])
        : "r"(a0), "r"(a1), "r"(a2), "r"(a3), "r"(b0), "r"(b1));
}

// ---------------- small prep kernels ----------------
__global__ void k_zero_xsum(){
    int i = blockIdx.x*256 + threadIdx.x;
    if(i < CC*EMB) g_xsum[i] = 0.f;
}

__global__ void k_prep_M(const float* __restrict__ wq, const float* __restrict__ wk){
    __shared__ float sq[DH*DH], sk[DH*DH];
    for(int i=threadIdx.x;i<DH*DH;i+=256){ sq[i]=wq[i]; sk[i]=wk[i]; }
    __syncthreads();
    for(int idx=threadIdx.x; idx<DH*DH; idx+=256){
        int d = idx/DH, e = idx%DH;
        float s = 0.f;
        #pragma unroll
        for(int o=0;o<DH;o++) s += sq[o*DH+d]*sk[o*DH+e];
        g_M[idx] = s;
    }
}

__global__ void k_xsum(const float* __restrict__ inp){
    int c = blockIdx.x, ch = blockIdx.y;
    const float* base = inp + ((size_t)c*TT + (size_t)ch*(TT/16))*EMB + threadIdx.x;
    float a0=0.f,a1=0.f,a2=0.f,a3=0.f;
    for(int t=0;t<TT/16;t++){
        const float* r = base + (size_t)t*EMB;
        a0 += r[0]; a1 += r[256]; a2 += r[512]; a3 += r[768];
    }
    atomicAdd(&g_xsum[c*EMB + threadIdx.x      ], a0);
    atomicAdd(&g_xsum[c*EMB + threadIdx.x + 256], a1);
    atomicAdd(&g_xsum[c*EMB + threadIdx.x + 512], a2);
    atomicAdd(&g_xsum[c*EMB + threadIdx.x + 768], a3);
}

__global__ void k_vsum(const float* __restrict__ wv){
    int c = blockIdx.x>>4, h = blockIdx.x&15;
    __shared__ float xs[DH];
    int o = threadIdx.x;
    xs[o] = g_xsum[c*EMB + h*DH + o];
    __syncthreads();
    float s = 0.f;
    #pragma unroll
    for(int d=0;d<DH;d++) s += xs[d]*wv[o*DH+d];
    g_vsum[c*EMB + h*DH + o] = s;
}

__global__ __launch_bounds__(256) void k_diag(const float* __restrict__ inp){
    __shared__ float Ms[DH][DH];
    __shared__ float Xs[64][DH+1];
    __shared__ float ds[64];
    int g0 = blockIdx.x*64;
    int tid = threadIdx.x, tx = tid&15, ty = tid>>4;
    for(int i=tid;i<DH*DH;i+=256) (&Ms[0][0])[i] = g_M[i];
    {
        const float* src = inp + (size_t)g0*DH;
        for(int i=tid;i<64*(DH/4);i+=256){
            int r = i/(DH/4), q = i%(DH/4);
            float4 v = *(const float4*)(src + (size_t)r*DH + q*4);
            Xs[r][q*4+0]=v.x; Xs[r][q*4+1]=v.y; Xs[r][q*4+2]=v.z; Xs[r][q*4+3]=v.w;
        }
    }
    __syncthreads();
    float acc[4][4] = {};
    #pragma unroll 8
    for(int k=0;k<DH;k++){
        float a[4], b[4];
        #pragma unroll
        for(int i=0;i<4;i++) a[i] = Xs[ty*4+i][k];
        #pragma unroll
        for(int j=0;j<4;j++) b[j] = Ms[k][tx*4+j];
        #pragma unroll
        for(int i=0;i<4;i++)
            #pragma unroll
            for(int j=0;j<4;j++) acc[i][j] += a[i]*b[j];
    }
    #pragma unroll
    for(int i=0;i<4;i++){
        float p = 0.f;
        #pragma unroll
        for(int j=0;j<4;j++) p += acc[i][j]*Xs[ty*4+i][tx*4+j];
        #pragma unroll
        for(int off=8;off;off>>=1) p += __shfl_down_sync(0xffffffffu, p, off, 16);
        if(tx==0) ds[ty*4+i] = p;
    }
    __syncthreads();
    if(tid < 64) g_w[g0+tid] = ds[tid]*(1.0f/32.0f);
}

__global__ void k_softmax(){
    int i = blockIdx.x*256 + threadIdx.x;
    if(i >= TT*NH) return;
    float v[CC];
    float m = -1e30f;
    #pragma unroll
    for(int c=0;c<CC;c++){ v[c] = g_w[(size_t)c*(TT*NH) + i]; m = fmaxf(m, v[c]); }
    float s = 0.f;
    #pragma unroll
    for(int c=0;c<CC;c++){ v[c] = __expf(v[c]-m); s += v[c]; }
    float inv = 1.f/s;
    #pragma unroll
    for(int c=0;c<CC;c++) g_w[(size_t)c*(TT*NH) + i] = v[c]*inv;
}

__device__ __forceinline__ float blk_reduce(float v, float* red){
    int lane = threadIdx.x&31, w = threadIdx.x>>5;
    #pragma unroll
    for(int off=16;off;off>>=1) v += __shfl_down_sync(0xffffffffu, v, off);
    if(lane==0) red[w] = v;
    __syncthreads();
    if(w==0){
        float x = (lane<8)? red[lane] : 0.f;
        #pragma unroll
        for(int off=4;off;off>>=1) x += __shfl_down_sync(0xffffffffu, x, off);
        if(lane==0) red[0] = x;
    }
    __syncthreads();
    float r = red[0];
    __syncthreads();
    return r;
}

// y = x2 + LN1(x2), written as split-bf16 interleaved
__global__ __launch_bounds__(256) void k_ln1(const float* __restrict__ inp,
                                             const float* __restrict__ g1,
                                             const float* __restrict__ b1){
    __shared__ float red[8];
    __shared__ float ws[NH];
    int row = blockIdx.x, c = row>>11;
    int tid = threadIdx.x;
    if(tid < NH) ws[tid] = g_w[(size_t)row*NH + tid];
    __syncthreads();
    float x[4]; float s = 0.f;
    #pragma unroll
    for(int j=0;j<4;j++){
        int e = tid + j*256;
        float v = inp[(size_t)row*EMB + e] + ws[e>>6]*g_vsum[c*EMB + e];
        x[j] = v; s += v;
    }
    float mu = blk_reduce(s, red)*(1.f/EMB);
    float q = 0.f;
    #pragma unroll
    for(int j=0;j<4;j++){ float d = x[j]-mu; q += d*d; }
    float rstd = rsqrtf(blk_reduce(q, red)*(1.f/EMB) + EPS_LN);
    #pragma unroll
    for(int j=0;j<4;j++){
        int e = tid + j*256;
        float val = x[j] + (x[j]-mu)*rstd*g1[e] + b1[e];
        __nv_bfloat16 hi = __float2bfloat16(val);
        __nv_bfloat16 lo = __float2bfloat16(val - __bfloat162float(hi));
        size_t base = (size_t)row*(2*EMB) + (size_t)(e>>5)*64 + (e&31);
        g_y2[base]    = hi;
        g_y2[base+32] = lo;
    }
}

// split fp32 matrix [rows][K] -> interleaved split-bf16 [rows][2K]
__global__ void k_split(const float* __restrict__ src, __nv_bfloat16* __restrict__ dst,
                        int K, int total4){
    int i = blockIdx.x*256 + threadIdx.x;
    if(i >= total4) return;
    int base = i*4;
    int row = base / K, k = base % K;
    float4 v = *(const float4*)(src + base);
    float x[4] = {v.x, v.y, v.z, v.w};
    uint32_t hw[2], lw[2];
    unsigned short hb[4], lb[4];
    #pragma unroll
    for(int u=0;u<4;u++){
        __nv_bfloat16 h = __float2bfloat16(x[u]);
        __nv_bfloat16 l = __float2bfloat16(x[u] - __bfloat162float(h));
        hb[u] = *(unsigned short*)&h;
        lb[u] = *(unsigned short*)&l;
    }
    hw[0] = (uint32_t)hb[0] | ((uint32_t)hb[1]<<16);
    hw[1] = (uint32_t)hb[2] | ((uint32_t)hb[3]<<16);
    lw[0] = (uint32_t)lb[0] | ((uint32_t)lb[1]<<16);
    lw[1] = (uint32_t)lb[2] | ((uint32_t)lb[3]<<16);
    __nv_bfloat16* d = dst + (size_t)row*(2*K) + (size_t)(k>>5)*64 + (k&31);
    *(uint2*)d      = make_uint2(hw[0], hw[1]);
    *(uint2*)(d+32) = make_uint2(lw[0], lw[1]);
}

__global__ __launch_bounds__(256) void k_ln2(float* __restrict__ out,
                                             const float* __restrict__ g2,
                                             const float* __restrict__ b2){
    __shared__ float red[8];
    int row = blockIdx.x;
    int tid = threadIdx.x;
    float x[4]; float s = 0.f;
    #pragma unroll
    for(int j=0;j<4;j++){
        int e = tid + j*256;
        x[j] = out[(size_t)row*EMB + e]; s += x[j];
    }
    float mu = blk_reduce(s, red)*(1.f/EMB);
    float q = 0.f;
    #pragma unroll
    for(int j=0;j<4;j++){ float d = x[j]-mu; q += d*d; }
    float rstd = rsqrtf(blk_reduce(q, red)*(1.f/EMB) + EPS_LN);
    #pragma unroll
    for(int j=0;j<4;j++){
        int e = tid + j*256;
        out[(size_t)row*EMB + e] = (x[j]-mu)*rstd*g2[e] + b2[e];
    }
}

// ---------------- split-bf16 warp-MMA GEMM ----------------
// C[M,N] = A[M,K] @ B[N,K]^T + bias, fp32 via 3-pass bf16 split.
// A,B interleaved [rows][2K]: 32-k block = [hi32|lo32] (64 cols = 128 B).
// CTA tile 128x128, BK=32 real k (=64 smem cols), 8 warps of 32x64,
// 4-stage cp.async pipeline, ldmatrix.x4 fragments, mma.m16n8k16 bf16.
#define PADC 72                      // smem cols per row (64 + 8 pad)
#define STRIDE_B (PADC*2)            // 144 bytes
#define TILE_BYTES (128*STRIDE_B)    // 18432
#define STAGE_BYTES (2*TILE_BYTES)   // A+B = 36864
#define NSTAGE 4
#define GEMM_SMEM (NSTAGE*STAGE_BYTES)  // 147456

template<int SPLIT_OUT>
__global__ __launch_bounds__(256, 1) void k_gemm_mma(
    const __nv_bfloat16* __restrict__ A,
    const __nv_bfloat16* __restrict__ B,
    const float* __restrict__ bias,
    float* __restrict__ Cf,
    __nv_bfloat16* __restrict__ Cs,
    int K2, int Nfull)
{
    extern __shared__ char smem_raw[];
    const uint32_t sb = smem_u32(smem_raw);
    const int tid = threadIdx.x;
    const int wid = tid >> 5, lane = tid & 31;
    const int wm = wid & 3, wn = wid >> 2;

    const size_t bm = (size_t)blockIdx.y * 128;
    const size_t bn = (size_t)blockIdx.x * 128;
    const int NKC = K2 >> 6;   // chunks of 64 interleaved cols (=32 real k)

    const __nv_bfloat16* Ag = A + bm * (size_t)K2;
    const __nv_bfloat16* Bg = B + bn * (size_t)K2;

    // per-thread copy map: 4 A-chunks + 4 B-chunks of 16B per stage
    const int crow[4] = { (tid)>>3 & 127, (tid+256)>>3, (tid+512)>>3, (tid+768)>>3 };
    const int cseg = (tid & 7) << 4;     // byte offset within 128B row

    auto load_stage = [&](int kc, int st){
        uint32_t sA = sb + st*STAGE_BYTES;
        uint32_t sB = sA + TILE_BYTES;
        const char* gA = (const char*)(Ag + (size_t)kc*64) + cseg;
        const char* gB = (const char*)(Bg + (size_t)kc*64) + cseg;
        size_t rstride = (size_t)K2 * 2;
        #pragma unroll
        for(int i=0;i<4;i++){
            int r = (tid + i*256) >> 3;
            cp16(sA + r*STRIDE_B + cseg, gA + (size_t)r*rstride);
        }
        #pragma unroll
        for(int i=0;i<4;i++){
            int r = (tid + i*256) >> 3;
            cp16(sB + r*STRIDE_B + cseg, gB + (size_t)r*rstride);
        }
        cp_commit();
    };

    float acc[2][8][4];
    #pragma unroll
    for(int i=0;i<2;i++)
        #pragma unroll
        for(int j=0;j<8;j++)
            #pragma unroll
            for(int q=0;q<4;q++) acc[i][j][q] = 0.f;

    // prefetch
    load_stage(0,0); load_stage(1,1); load_stage(2,2);

    const uint32_t lrow = lane & 15;          // ldmatrix row within tile
    const uint32_t lcol = (lane >> 4) << 4;   // +16B for upper half

    for(int kc=0; kc<NKC; kc++){
        cp_wait2();
        __syncthreads();
        if (kc+3 < NKC) load_stage(kc+3, (kc+3)&3);

        uint32_t sA = sb + (kc&3)*STAGE_BYTES;
        uint32_t sB = sA + TILE_BYTES;
        uint32_t aBase = sA + (wm*32 + lrow)*STRIDE_B + lcol;
        uint32_t bBase = sB + (wn*64 + lrow)*STRIDE_B + lcol;

        #pragma unroll
        for(int s=0;s<2;s++){
            // A frags: [prec][mtile][4]
            uint32_t af[2][2][4];
            #pragma unroll
            for(int p=0;p<2;p++)
                #pragma unroll
                for(int i=0;i<2;i++)
                    ldm4(aBase + i*16*STRIDE_B + (p*64 + s*32),
                         af[p][i][0], af[p][i][1], af[p][i][2], af[p][i][3]);
            // B frags: [prec][jt][4], jt covers n16
            uint32_t bf[2][4][4];
            #pragma unroll
            for(int p=0;p<2;p++)
                #pragma unroll
                for(int j=0;j<4;j++)
                    ldm4(bBase + j*16*STRIDE_B + (p*64 + s*32),
                         bf[p][j][0], bf[p][j][1], bf[p][j][2], bf[p][j][3]);

            // 3 passes: (hi,hi), (hi,lo), (lo,hi)
            #pragma unroll
            for(int pass=0;pass<3;pass++){
                int pa = (pass==2) ? 1 : 0;
                int pb = (pass==1) ? 1 : 0;
                #pragma unroll
                for(int i=0;i<2;i++){
                    #pragma unroll
                    for(int j=0;j<4;j++){
                        // n8 tile 2j   : b regs (r0, r2)
                        mma16816(acc[i][2*j],   af[pa][i][0], af[pa][i][1], af[pa][i][2], af[pa][i][3],
                                 bf[pb][j][0], bf[pb][j][2]);
                        // n8 tile 2j+1 : b regs (r1, r3)
                        mma16816(acc[i][2*j+1], af[pa][i][0], af[pa][i][1], af[pa][i][2], af[pa][i][3],
                                 bf[pb][j][1], bf[pb][j][3]);
                    }
                }
            }
        }
        __syncthreads();
    }
    cp_wait0();

    // epilogue
    const int r4 = lane >> 2, c2 = (lane & 3) << 1;
    #pragma unroll
    for(int i=0;i<2;i++){
        size_t row0 = bm + wm*32 + i*16 + r4;
        #pragma unroll
        for(int j=0;j<8;j++){
            size_t n0 = bn + wn*64 + j*8 + c2;
            float b0 = bias[n0], b1 = bias[n0+1];
            float v00 = acc[i][j][0] + b0, v01 = acc[i][j][1] + b1;
            float v10 = acc[i][j][2] + b0, v11 = acc[i][j][3] + b1;
            if (SPLIT_OUT){
                size_t off = (size_t)(n0>>5)*64 + (n0&31);
                __nv_bfloat16* d0 = Cs + row0*(size_t)(2*Nfull) + off;
                __nv_bfloat16* d1 = Cs + (row0+8)*(size_t)(2*Nfull) + off;
                __nv_bfloat16 h00 = __float2bfloat16(v00), h01 = __float2bfloat16(v01);
                __nv_bfloat16 h10 = __float2bfloat16(v10), h11 = __float2bfloat16(v11);
                __nv_bfloat16 l00 = __float2bfloat16(v00 - __bfloat162float(h00));
                __nv_bfloat16 l01 = __float2bfloat16(v01 - __bfloat162float(h01));
                __nv_bfloat16 l10 = __float2bfloat16(v10 - __bfloat162float(h10));
                __nv_bfloat16 l11 = __float2bfloat16(v11 - __bfloat162float(h11));
                *(uint32_t*)d0      = (uint32_t)(*(unsigned short*)&h00) | ((uint32_t)(*(unsigned short*)&h01)<<16);
                *(uint32_t*)(d0+32) = (uint32_t)(*(unsigned short*)&l00) | ((uint32_t)(*(unsigned short*)&l01)<<16);
                *(uint32_t*)d1      = (uint32_t)(*(unsigned short*)&h10) | ((uint32_t)(*(unsigned short*)&h11)<<16);
                *(uint32_t*)(d1+32) = (uint32_t)(*(unsigned short*)&l10) | ((uint32_t)(*(unsigned short*)&l11)<<16);
            } else {
                float* d0 = Cf + row0*(size_t)Nfull + n0;
                float* d1 = Cf + (row0+8)*(size_t)Nfull + n0;
                d0[0] = v00; d0[1] = v01;
                d1[0] = v10; d1[1] = v11;
            }
        }
    }
}

// ---------------- launch ----------------
extern "C" void kernel_launch(void* const* d_in, const int* in_sizes, int n_in,
                              void* d_out, int out_size){
    const float* inp   = (const float*)d_in[0];
    const float* wq    = (const float*)d_in[1];
    const float* wk    = (const float*)d_in[2];
    const float* wv    = (const float*)d_in[3];
    const float* ln1_g = (const float*)d_in[4];
    const float* ln1_b = (const float*)d_in[5];
    const float* fc1_w = (const float*)d_in[6];
    const float* fc1_b = (const float*)d_in[7];
    const float* fc2_w = (const float*)d_in[8];
    const float* fc2_b = (const float*)d_in[9];
    const float* ln2_g = (const float*)d_in[10];
    const float* ln2_b = (const float*)d_in[11];
    float* out = (float*)d_out;

    __nv_bfloat16 *y2p=nullptr, *h2p=nullptr, *w1p=nullptr, *w2p=nullptr;
    cudaGetSymbolAddress((void**)&y2p, g_y2);
    cudaGetSymbolAddress((void**)&h2p, g_h2);
    cudaGetSymbolAddress((void**)&w1p, g_w1);
    cudaGetSymbolAddress((void**)&w2p, g_w2);

    cudaFuncSetAttribute(k_gemm_mma<1>, cudaFuncAttributeMaxDynamicSharedMemorySize, GEMM_SMEM);
    cudaFuncSetAttribute(k_gemm_mma<0>, cudaFuncAttributeMaxDynamicSharedMemorySize, GEMM_SMEM);

    k_zero_xsum<<<(CC*EMB+255)/256, 256>>>();
    k_prep_M<<<1, 256>>>(wq, wk);
    k_xsum<<<dim3(CC,16), 256>>>(inp);
    k_vsum<<<CC*NH, 64>>>(wv);
    k_diag<<<NVEC/64, 256>>>(inp);
    k_softmax<<<(TT*NH+255)/256, 256>>>();
    k_ln1<<<NROWS, 256>>>(inp, ln1_g, ln1_b);

    k_split<<<(MAPD*EMB/4 + 255)/256, 256>>>(fc1_w, w1p, EMB,  MAPD*EMB/4);
    k_split<<<(EMB*MAPD/4 + 255)/256, 256>>>(fc2_w, w2p, MAPD, EMB*MAPD/4);

    // h = y @ fc1_w^T + b1  (split-bf16 out)
    k_gemm_mma<1><<<dim3(MAPD/128, NROWS/128), 256, GEMM_SMEM>>>(
        y2p, w1p, fc1_b, nullptr, h2p, 2*EMB, MAPD);
    // out = h @ fc2_w^T + b2 (fp32 out)
    k_gemm_mma<0><<<dim3(EMB/128, NROWS/128), 256, GEMM_SMEM>>>(
        h2p, w2p, fc2_b, out, nullptr, 2*MAPD, EMB);

    k_ln2<<<NROWS, 256>>>(out, ln2_g, ln2_b);
}

// round 4
// speedup vs baseline: 2.3386x; 1.0576x over previous
#include <cuda_runtime.h>
#include <cuda_bf16.h>
#include <cstdint>

#define CC 32
#define TT 2048
#define EMB 1024
#define NH 16
#define DH 64
#define MAPD 4096
#define NROWS (CC*TT)          // 65536
#define NVEC (NROWS*NH)
#define EPS_LN 1e-5f

// ---------------- scratch (static device globals) ----------------
__device__ float g_M[DH*DH];
__device__ float g_xpart[512*EMB];              // 16 partial sums per c
__device__ float g_vsum[CC*EMB];
__device__ float g_w[NROWS*NH];                 // raw diag scores /32
// split-bf16 interleaved: row-major [rows][2*K], each 32-k block stored [hi(32)|lo(32)]
__device__ __align__(128) __nv_bfloat16 g_y2[(size_t)NROWS*(2*EMB)];    // 268 MB
__device__ __align__(128) __nv_bfloat16 g_h2[(size_t)NROWS*(2*MAPD)];   // 1.07 GB
__device__ __align__(128) __nv_bfloat16 g_w1[(size_t)MAPD*(2*EMB)];     // 16 MB
__device__ __align__(128) __nv_bfloat16 g_w2[(size_t)EMB*(2*MAPD)];     // 16 MB

// ---------------- helpers ----------------
__device__ __forceinline__ uint32_t smem_u32(const void* p){
    uint32_t a;
    asm("{ .reg .u64 t; cvta.to.shared.u64 t, %1; cvt.u32.u64 %0, t; }" : "=r"(a) : "l"(p));
    return a;
}
__device__ __forceinline__ void cp16(uint32_t dst, const void* src){
    asm volatile("cp.async.cg.shared.global [%0], [%1], 16;" :: "r"(dst), "l"(src) : "memory");
}
__device__ __forceinline__ void cp_commit(){ asm volatile("cp.async.commit_group;" ::: "memory"); }
__device__ __forceinline__ void cp_wait2(){ asm volatile("cp.async.wait_group 2;" ::: "memory"); }
__device__ __forceinline__ void cp_wait0(){ asm volatile("cp.async.wait_group 0;" ::: "memory"); }

__device__ __forceinline__ void ldm4(uint32_t a, uint32_t* r){
    asm volatile("ldmatrix.sync.aligned.m8n8.x4.shared.b16 {%0,%1,%2,%3}, [%4];"
        : "=r"(r[0]), "=r"(r[1]), "=r"(r[2]), "=r"(r[3]) : "r"(a));
}
__device__ __forceinline__ void mma16816(float* d, const uint32_t* a, uint32_t b0, uint32_t b1){
    asm volatile("mma.sync.aligned.m16n8k16.row.col.f32.bf16.bf16.f32 "
        "{%0,%1,%2,%3}, {%4,%5,%6,%7}, {%8,%9}, {%0,%1,%2,%3};"
        : "+f"(d[0]), "+f"(d[1]), "+f"(d[2]), "+f"(d[3])
        : "r"(a[0]), "r"(a[1]), "r"(a[2]), "r"(a[3]), "r"(b0), "r"(b1));
}

// ---------------- kernel 1: partial xsum + prep_M ----------------
// grid 513 x 256: blocks 0..511 -> xsum partials, block 512 -> M = Wq^T Wk
__global__ void k_pre(const float* __restrict__ inp,
                      const float* __restrict__ wq, const float* __restrict__ wk){
    int b = blockIdx.x, tid = threadIdx.x;
    if(b == 512){
        __shared__ float sq[DH*DH], sk[DH*DH];
        for(int i=tid;i<DH*DH;i+=256){ sq[i]=wq[i]; sk[i]=wk[i]; }
        __syncthreads();
        for(int idx=tid; idx<DH*DH; idx+=256){
            int d = idx/DH, e = idx%DH;
            float s = 0.f;
            #pragma unroll
            for(int o=0;o<DH;o++) s += sq[o*DH+d]*sk[o*DH+e];
            g_M[idx] = s;
        }
        return;
    }
    int c = b>>4, seg = b&15;
    size_t base = ((size_t)c*TT + (size_t)seg*128)*EMB;
    #pragma unroll
    for(int j=0;j<4;j++){
        int e = tid + j*256;
        float acc = 0.f;
        const float* p = inp + base + e;
        #pragma unroll 4
        for(int t=0;t<128;t++) acc += p[(size_t)t*EMB];
        g_xpart[(size_t)b*EMB + e] = acc;
    }
}

// ---------------- kernel 2: diag scores + vsum ----------------
// blocks 0..16383: diag; blocks 16384..16895: vsum
__global__ __launch_bounds__(256) void k_diagv(const float* __restrict__ inp,
                                               const float* __restrict__ wv){
    if(blockIdx.x >= 16384){
        int b2 = blockIdx.x - 16384;
        int c = b2>>4, h = b2&15;
        __shared__ float xs[DH];
        int tid = threadIdx.x;
        if(tid < DH){
            float s = 0.f;
            #pragma unroll
            for(int seg=0;seg<16;seg++) s += g_xpart[(size_t)(c*16+seg)*EMB + h*DH + tid];
            xs[tid] = s;
        }
        __syncthreads();
        if(tid < DH){
            float s = 0.f;
            #pragma unroll
            for(int d=0;d<DH;d++) s += xs[d]*wv[tid*DH+d];
            g_vsum[c*EMB + h*DH + tid] = s;
        }
        return;
    }
    __shared__ float Ms[DH][DH];
    __shared__ float Xs[64][DH+1];
    __shared__ float ds[64];
    int g0 = blockIdx.x*64;
    int tid = threadIdx.x, tx = tid&15, ty = tid>>4;
    for(int i=tid;i<DH*DH;i+=256) (&Ms[0][0])[i] = g_M[i];
    {
        const float* src = inp + (size_t)g0*DH;
        for(int i=tid;i<64*(DH/4);i+=256){
            int r = i/(DH/4), q = i%(DH/4);
            float4 v = *(const float4*)(src + (size_t)r*DH + q*4);
            Xs[r][q*4+0]=v.x; Xs[r][q*4+1]=v.y; Xs[r][q*4+2]=v.z; Xs[r][q*4+3]=v.w;
        }
    }
    __syncthreads();
    float acc[4][4] = {};
    #pragma unroll 8
    for(int k=0;k<DH;k++){
        float a[4], b[4];
        #pragma unroll
        for(int i=0;i<4;i++) a[i] = Xs[ty*4+i][k];
        #pragma unroll
        for(int j=0;j<4;j++) b[j] = Ms[k][tx*4+j];
        #pragma unroll
        for(int i=0;i<4;i++)
            #pragma unroll
            for(int j=0;j<4;j++) acc[i][j] += a[i]*b[j];
    }
    #pragma unroll
    for(int i=0;i<4;i++){
        float p = 0.f;
        #pragma unroll
        for(int j=0;j<4;j++) p += acc[i][j]*Xs[ty*4+i][tx*4+j];
        #pragma unroll
        for(int off=8;off;off>>=1) p += __shfl_down_sync(0xffffffffu, p, off, 16);
        if(tx==0) ds[ty*4+i] = p;
    }
    __syncthreads();
    if(tid < 64) g_w[g0+tid] = ds[tid]*(1.0f/32.0f);
}

// ---------------- block reduction ----------------
__device__ __forceinline__ float blk_reduce(float v, float* red){
    int lane = threadIdx.x&31, w = threadIdx.x>>5;
    #pragma unroll
    for(int off=16;off;off>>=1) v += __shfl_down_sync(0xffffffffu, v, off);
    if(lane==0) red[w] = v;
    __syncthreads();
    if(w==0){
        float x = (lane<8)? red[lane] : 0.f;
        #pragma unroll
        for(int off=4;off;off>>=1) x += __shfl_down_sync(0xffffffffu, x, off);
        if(lane==0) red[0] = x;
    }
    __syncthreads();
    float r = red[0];
    __syncthreads();
    return r;
}

// ---------------- kernel 3: softmax (inline) + residual + LN1, split-bf16 out ----------------
__global__ __launch_bounds__(256) void k_ln1(const float* __restrict__ inp,
                                             const float* __restrict__ g1,
                                             const float* __restrict__ b1){
    __shared__ float red[8];
    __shared__ float ws[NH];
    int row = blockIdx.x, c = row>>11, t = row&2047;
    int tid = threadIdx.x;
    if(tid < NH){
        int h = tid;
        size_t idx = (size_t)t*NH + h;
        float d[CC], m = -1e30f;
        #pragma unroll
        for(int c2=0;c2<CC;c2++){
            d[c2] = g_w[(size_t)c2*(TT*NH) + idx];
            m = fmaxf(m, d[c2]);
        }
        float s = 0.f;
        #pragma unroll
        for(int c2=0;c2<CC;c2++) s += __expf(d[c2]-m);
        ws[h] = __expf(d[c]-m) / s;
    }
    __syncthreads();
    float x[4]; float s = 0.f;
    #pragma unroll
    for(int j=0;j<4;j++){
        int e = tid + j*256;
        float v = inp[(size_t)row*EMB + e] + ws[e>>6]*g_vsum[c*EMB + e];
        x[j] = v; s += v;
    }
    float mu = blk_reduce(s, red)*(1.f/EMB);
    float q = 0.f;
    #pragma unroll
    for(int j=0;j<4;j++){ float d = x[j]-mu; q += d*d; }
    float rstd = rsqrtf(blk_reduce(q, red)*(1.f/EMB) + EPS_LN);
    #pragma unroll
    for(int j=0;j<4;j++){
        int e = tid + j*256;
        float val = x[j] + (x[j]-mu)*rstd*g1[e] + b1[e];
        __nv_bfloat16 hi = __float2bfloat16(val);
        __nv_bfloat16 lo = __float2bfloat16(val - __bfloat162float(hi));
        size_t base = (size_t)row*(2*EMB) + (size_t)(e>>5)*64 + (e&31);
        g_y2[base]    = hi;
        g_y2[base+32] = lo;
    }
}

// ---------------- kernel 4/5: split fp32 -> interleaved split-bf16 ----------------
__global__ void k_split(const float* __restrict__ src, __nv_bfloat16* __restrict__ dst,
                        int K, int total4){
    int i = blockIdx.x*256 + threadIdx.x;
    if(i >= total4) return;
    int base = i*4;
    int row = base / K, k = base % K;
    float4 v = *(const float4*)(src + base);
    float x[4] = {v.x, v.y, v.z, v.w};
    uint32_t hw[2], lw[2];
    unsigned short hb[4], lb[4];
    #pragma unroll
    for(int u=0;u<4;u++){
        __nv_bfloat16 h = __float2bfloat16(x[u]);
        __nv_bfloat16 l = __float2bfloat16(x[u] - __bfloat162float(h));
        hb[u] = *(unsigned short*)&h;
        lb[u] = *(unsigned short*)&l;
    }
    hw[0] = (uint32_t)hb[0] | ((uint32_t)hb[1]<<16);
    hw[1] = (uint32_t)hb[2] | ((uint32_t)hb[3]<<16);
    lw[0] = (uint32_t)lb[0] | ((uint32_t)lb[1]<<16);
    lw[1] = (uint32_t)lb[2] | ((uint32_t)lb[3]<<16);
    __nv_bfloat16* d = dst + (size_t)row*(2*K) + (size_t)(k>>5)*64 + (k&31);
    *(uint2*)d      = make_uint2(hw[0], hw[1]);
    *(uint2*)(d+32) = make_uint2(lw[0], lw[1]);
}

// ---------------- kernel 8: final LN2 ----------------
__global__ __launch_bounds__(256) void k_ln2(float* __restrict__ out,
                                             const float* __restrict__ g2,
                                             const float* __restrict__ b2){
    __shared__ float red[8];
    int row = blockIdx.x;
    int tid = threadIdx.x;
    float x[4]; float s = 0.f;
    #pragma unroll
    for(int j=0;j<4;j++){
        int e = tid + j*256;
        x[j] = out[(size_t)row*EMB + e]; s += x[j];
    }
    float mu = blk_reduce(s, red)*(1.f/EMB);
    float q = 0.f;
    #pragma unroll
    for(int j=0;j<4;j++){ float d = x[j]-mu; q += d*d; }
    float rstd = rsqrtf(blk_reduce(q, red)*(1.f/EMB) + EPS_LN);
    #pragma unroll
    for(int j=0;j<4;j++){
        int e = tid + j*256;
        out[(size_t)row*EMB + e] = (x[j]-mu)*rstd*g2[e] + b2[e];
    }
}

// ---------------- split-bf16 warp-MMA GEMM ----------------
// C[M,N] = A[M,K] @ B[N,K]^T + bias, fp32 via 3-pass bf16 split.
// CTA 128x128, 512 threads (16 warps, 4x4), warp tile 32x32.
// BK=32 real k (=64 interleaved cols = 128B/row), 4-stage cp.async, 1 sync/chunk.
#define STRIDE_B 144                   // 128B row + 16B pad
#define STAGE_BYTES (256*STRIDE_B)     // A(128 rows) + B(128 rows) = 36864
#define NSTAGE 4
#define GEMM_SMEM (NSTAGE*STAGE_BYTES) // 147456

template<int SPLIT_OUT>
__global__ __launch_bounds__(512, 1) void k_gemm_mma(
    const __nv_bfloat16* __restrict__ A,
    const __nv_bfloat16* __restrict__ B,
    const float* __restrict__ bias,
    float* __restrict__ Cf,
    __nv_bfloat16* __restrict__ Cs,
    int K2, int Nfull)
{
    extern __shared__ char smem_raw[];
    const uint32_t sb = smem_u32(smem_raw);
    const int tid = threadIdx.x;
    const int wid = tid >> 5, lane = tid & 31;
    const int wm = wid & 3, wn = wid >> 2;

    const size_t bm = (size_t)blockIdx.y * 128;
    const size_t bn = (size_t)blockIdx.x * 128;
    const int NKC = K2 >> 6;

    const char* Ag = (const char*)(A + bm * (size_t)K2);
    const char* Bg = (const char*)(B + bn * (size_t)K2);
    const size_t rstride = (size_t)K2 * 2;

    auto load_stage = [&](int kc){
        uint32_t st = sb + (kc&3)*STAGE_BYTES;
        size_t gofs = (size_t)kc*128;
        #pragma unroll
        for(int i=0;i<4;i++){
            int idx = tid + i*512;
            int r = idx >> 3;
            int cs = (idx & 7) << 4;
            if (r < 128)
                cp16(st + r*STRIDE_B + cs, Ag + (size_t)r*rstride + gofs + cs);
            else
                cp16(st + r*STRIDE_B + cs, Bg + (size_t)(r-128)*rstride + gofs + cs);
        }
        cp_commit();
    };

    float acc[2][4][4];
    #pragma unroll
    for(int i=0;i<2;i++)
        #pragma unroll
        for(int j=0;j<4;j++)
            #pragma unroll
            for(int q=0;q<4;q++) acc[i][j][q] = 0.f;

    load_stage(0); load_stage(1); load_stage(2);

    const uint32_t lrow = lane & 15;
    const uint32_t lcol = (lane >> 4) << 4;

    for(int kc=0; kc<NKC; kc++){
        cp_wait2();
        __syncthreads();
        if (kc+3 < NKC) load_stage(kc+3);

        uint32_t sA = sb + (kc&3)*STAGE_BYTES;
        uint32_t sB = sA + 128*STRIDE_B;
        uint32_t aBase = sA + (wm*32 + lrow)*STRIDE_B + lcol;
        uint32_t bBase = sB + (wn*32 + lrow)*STRIDE_B + lcol;

        #pragma unroll
        for(int s=0;s<2;s++){
            uint32_t af[2][2][4];   // [prec][mtile]
            uint32_t bf[2][2][4];   // [prec][ntile16]
            #pragma unroll
            for(int p=0;p<2;p++)
                #pragma unroll
                for(int i=0;i<2;i++)
                    ldm4(aBase + i*16*STRIDE_B + (p*64 + s*32), af[p][i]);
            #pragma unroll
            for(int p=0;p<2;p++)
                #pragma unroll
                for(int j=0;j<2;j++)
                    ldm4(bBase + j*16*STRIDE_B + (p*64 + s*32), bf[p][j]);

            #pragma unroll
            for(int pass=0;pass<3;pass++){
                const int pa = (pass==2) ? 1 : 0;
                const int pb = (pass==1) ? 1 : 0;
                #pragma unroll
                for(int i=0;i<2;i++){
                    #pragma unroll
                    for(int j=0;j<2;j++){
                        mma16816(acc[i][2*j],   af[pa][i], bf[pb][j][0], bf[pb][j][2]);
                        mma16816(acc[i][2*j+1], af[pa][i], bf[pb][j][1], bf[pb][j][3]);
                    }
                }
            }
        }
    }
    cp_wait0();

    // epilogue
    const int r4 = lane >> 2, c2 = (lane & 3) << 1;
    #pragma unroll
    for(int i=0;i<2;i++){
        size_t row0 = bm + wm*32 + i*16 + r4;
        #pragma unroll
        for(int j=0;j<4;j++){
            size_t n0 = bn + wn*32 + j*8 + c2;
            float b0 = bias[n0], b1 = bias[n0+1];
            float v00 = acc[i][j][0] + b0, v01 = acc[i][j][1] + b1;
            float v10 = acc[i][j][2] + b0, v11 = acc[i][j][3] + b1;
            if (SPLIT_OUT){
                size_t off = (size_t)(n0>>5)*64 + (n0&31);
                __nv_bfloat16* d0 = Cs + row0*(size_t)(2*Nfull) + off;
                __nv_bfloat16* d1 = Cs + (row0+8)*(size_t)(2*Nfull) + off;
                __nv_bfloat16 h00 = __float2bfloat16(v00), h01 = __float2bfloat16(v01);
                __nv_bfloat16 h10 = __float2bfloat16(v10), h11 = __float2bfloat16(v11);
                __nv_bfloat16 l00 = __float2bfloat16(v00 - __bfloat162float(h00));
                __nv_bfloat16 l01 = __float2bfloat16(v01 - __bfloat162float(h01));
                __nv_bfloat16 l10 = __float2bfloat16(v10 - __bfloat162float(h10));
                __nv_bfloat16 l11 = __float2bfloat16(v11 - __bfloat162float(h11));
                *(uint32_t*)d0      = (uint32_t)(*(unsigned short*)&h00) | ((uint32_t)(*(unsigned short*)&h01)<<16);
                *(uint32_t*)(d0+32) = (uint32_t)(*(unsigned short*)&l00) | ((uint32_t)(*(unsigned short*)&l01)<<16);
                *(uint32_t*)d1      = (uint32_t)(*(unsigned short*)&h10) | ((uint32_t)(*(unsigned short*)&h11)<<16);
                *(uint32_t*)(d1+32) = (uint32_t)(*(unsigned short*)&l10) | ((uint32_t)(*(unsigned short*)&l11)<<16);
            } else {
                float* d0 = Cf + row0*(size_t)Nfull + n0;
                float* d1 = Cf + (row0+8)*(size_t)Nfull + n0;
                d0[0] = v00; d0[1] = v01;
                d1[0] = v10; d1[1] = v11;
            }
        }
    }
}

// ---------------- launch ----------------
extern "C" void kernel_launch(void* const* d_in, const int* in_sizes, int n_in,
                              void* d_out, int out_size){
    const float* inp   = (const float*)d_in[0];
    const float* wq    = (const float*)d_in[1];
    const float* wk    = (const float*)d_in[2];
    const float* wv    = (const float*)d_in[3];
    const float* ln1_g = (const float*)d_in[4];
    const float* ln1_b = (const float*)d_in[5];
    const float* fc1_w = (const float*)d_in[6];
    const float* fc1_b = (const float*)d_in[7];
    const float* fc2_w = (const float*)d_in[8];
    const float* fc2_b = (const float*)d_in[9];
    const float* ln2_g = (const float*)d_in[10];
    const float* ln2_b = (const float*)d_in[11];
    float* out = (float*)d_out;

    __nv_bfloat16 *y2p=nullptr, *h2p=nullptr, *w1p=nullptr, *w2p=nullptr;
    cudaGetSymbolAddress((void**)&y2p, g_y2);
    cudaGetSymbolAddress((void**)&h2p, g_h2);
    cudaGetSymbolAddress((void**)&w1p, g_w1);
    cudaGetSymbolAddress((void**)&w2p, g_w2);

    cudaFuncSetAttribute(k_gemm_mma<1>, cudaFuncAttributeMaxDynamicSharedMemorySize, GEMM_SMEM);
    cudaFuncSetAttribute(k_gemm_mma<0>, cudaFuncAttributeMaxDynamicSharedMemorySize, GEMM_SMEM);

    // launches 1..5
    k_pre<<<513, 256>>>(inp, wq, wk);
    k_diagv<<<16384+512, 256>>>(inp, wv);
    k_ln1<<<NROWS, 256>>>(inp, ln1_g, ln1_b);
    k_split<<<(MAPD*EMB/4 + 255)/256, 256>>>(fc1_w, w1p, EMB,  MAPD*EMB/4);
    k_split<<<(EMB*MAPD/4 + 255)/256, 256>>>(fc2_w, w2p, MAPD, EMB*MAPD/4);

    // launch 6: h = y @ fc1_w^T + b1  (split-bf16 out) -- profiled by ncu -s 5 -c 1
    k_gemm_mma<1><<<dim3(MAPD/128, NROWS/128), 512, GEMM_SMEM>>>(
        y2p, w1p, fc1_b, nullptr, h2p, 2*EMB, MAPD);
    // launch 7: out = h @ fc2_w^T + b2 (fp32 out)
    k_gemm_mma<0><<<dim3(EMB/128, NROWS/128), 512, GEMM_SMEM>>>(
        h2p, w2p, fc2_b, out, nullptr, 2*MAPD, EMB);

    k_ln2<<<NROWS, 256>>>(out, ln2_g, ln2_b);
}